// round 1
// baseline (speedup 1.0000x reference)
#include <cuda_runtime.h>
#include <cstdint>

// ---------------------------------------------------------------------------
// Problem constants
// ---------------------------------------------------------------------------
#define BATCH    64
#define NPTS     512
#define NNODES   (BATCH * NPTS)   // 32768
#define KNN      8
#define F_IN     6
#define DH       336              // hidden dim of every edge MLP
#define DO       256              // output dim of every conv
#define CATDIM   1030             // 6 + 4*256

// ---------------------------------------------------------------------------
// Static device scratch (no runtime allocation allowed)
// ---------------------------------------------------------------------------
__device__ float g_sq  [NNODES];
__device__ float g_D   [(size_t)BATCH * NPTS * NPTS];      // 64 MB
__device__ int   g_idx [NNODES * KNN];
__device__ float g_wcat[256 * (2 * DH)];                   // [F,672], F<=256
__device__ float g_PQ  [(size_t)NNODES * (2 * DH)];        // P||Q, 88 MB
__device__ float g_x1  [(size_t)NNODES * DO];
__device__ float g_x2  [(size_t)NNODES * DO];
__device__ float g_x3  [(size_t)NNODES * DO];
__device__ float g_x4  [(size_t)NNODES * DO];
__device__ float g_cat [(size_t)NNODES * CATDIM];          // 135 MB
__device__ float g_h   [(size_t)NNODES * DH];
__device__ float g_h2  [(size_t)NNODES * DO];
__device__ float g_pool[BATCH * DO];

__device__ __forceinline__ float lrelu(float v) { return v >= 0.f ? v : 0.01f * v; }

// ---------------------------------------------------------------------------
// 1) squared norms, one warp per node
// ---------------------------------------------------------------------------
__global__ void sqnorm_kernel(const float* __restrict__ X, int F) {
    int node = blockIdx.x * 8 + (threadIdx.x >> 5);
    int lane = threadIdx.x & 31;
    const float* row = X + (size_t)node * F;
    float s = 0.f;
    for (int f = lane; f < F; f += 32) { float v = row[f]; s += v * v; }
    #pragma unroll
    for (int o = 16; o; o >>= 1) s += __shfl_xor_sync(0xFFFFFFFFu, s, o);
    if (lane == 0) g_sq[node] = s;
}

// ---------------------------------------------------------------------------
// 2) pairwise distance matrix, 32x32 tile per block, 2x2 per thread
//    grid: (jTile=16, iTile=16, batch=64), block 256
// ---------------------------------------------------------------------------
__global__ void dist_kernel(const float* __restrict__ X, int F) {
    __shared__ float As[32][17];
    __shared__ float Bs[32][17];
    int b  = blockIdx.z;
    int i0 = blockIdx.y * 32;
    int j0 = blockIdx.x * 32;
    int tid = threadIdx.x;
    int tx = tid & 15, ty = tid >> 4;

    float acc00 = 0.f, acc01 = 0.f, acc10 = 0.f, acc11 = 0.f;

    for (int f0 = 0; f0 < F; f0 += 16) {
        #pragma unroll
        for (int s = 0; s < 2; s++) {
            int r = (tid >> 4) + s * 16;
            int c = tid & 15;
            float av = 0.f, bv = 0.f;
            if (f0 + c < F) {
                av = X[((size_t)(b * NPTS + i0 + r)) * F + f0 + c];
                bv = X[((size_t)(b * NPTS + j0 + r)) * F + f0 + c];
            }
            As[r][c] = av;
            Bs[r][c] = bv;
        }
        __syncthreads();
        #pragma unroll
        for (int ff = 0; ff < 16; ff++) {
            float a0 = As[2 * ty + 0][ff];
            float a1 = As[2 * ty + 1][ff];
            float b0 = Bs[2 * tx + 0][ff];
            float b1 = Bs[2 * tx + 1][ff];
            acc00 += a0 * b0; acc01 += a0 * b1;
            acc10 += a1 * b0; acc11 += a1 * b1;
        }
        __syncthreads();
    }

    int gi0 = i0 + 2 * ty, gj0 = j0 + 2 * tx;
    float si0 = g_sq[b * NPTS + gi0], si1 = g_sq[b * NPTS + gi0 + 1];
    float sj0 = g_sq[b * NPTS + gj0], sj1 = g_sq[b * NPTS + gj0 + 1];
    size_t base = ((size_t)b * NPTS + gi0) * NPTS + gj0;
    g_D[base]            = si0 + sj0 - 2.f * acc00;
    g_D[base + 1]        = si0 + sj1 - 2.f * acc01;
    g_D[base + NPTS]     = si1 + sj0 - 2.f * acc10;
    g_D[base + NPTS + 1] = si1 + sj1 - 2.f * acc11;
}

// ---------------------------------------------------------------------------
// 3) top-8 smallest per row (tie-break: lowest index). One block per row.
// ---------------------------------------------------------------------------
__global__ void topk_kernel() {
    int row = blockIdx.x;          // b*512 + i
    int b = row >> 9;
    const float* drow = g_D + (size_t)row * NPTS;
    __shared__ float sv[NPTS];
    __shared__ float rv[256];
    __shared__ int   ri[256];
    int t = threadIdx.x;
    sv[t] = drow[t];
    sv[t + 256] = drow[t + 256];
    __syncthreads();
    for (int k = 0; k < KNN; k++) {
        float v0 = sv[t], v1 = sv[t + 256];
        float bv; int bi;
        if (v0 <= v1) { bv = v0; bi = t; } else { bv = v1; bi = t + 256; }
        rv[t] = bv; ri[t] = bi;
        __syncthreads();
        for (int s = 128; s > 0; s >>= 1) {
            if (t < s) {
                float ov = rv[t + s]; int oi = ri[t + s];
                if (ov < rv[t] || (ov == rv[t] && oi < ri[t])) { rv[t] = ov; ri[t] = oi; }
            }
            __syncthreads();
        }
        if (t == 0) {
            g_idx[row * KNN + k] = b * NPTS + ri[0];
            sv[ri[0]] = 3.4e38f;
        }
        __syncthreads();
    }
}

// ---------------------------------------------------------------------------
// 4) Wcat transform: [F,672] = [Wtop - Wbot || Wbot]  from w1 [2F,336]
// ---------------------------------------------------------------------------
__global__ void wcat_kernel(const float* __restrict__ w1, int F) {
    int e = blockIdx.x * blockDim.x + threadIdx.x;
    if (e >= F * DH) return;
    int f = e / DH, h = e % DH;
    float top = w1[f * DH + h];
    float bot = w1[(F + f) * DH + h];
    g_wcat[f * (2 * DH) + h]       = top - bot;
    g_wcat[f * (2 * DH) + DH + h]  = bot;
}

// ---------------------------------------------------------------------------
// 5) Generic tiled fp32 GEMM: C[M,N] = A[M,K]@B[K,N] (+bias)(+lrelu)
//    BM=BN=64, BK=16, 256 threads, 4x4 per thread. M % 64 == 0 assumed.
// ---------------------------------------------------------------------------
__global__ void gemm_kernel(const float* __restrict__ A, const float* __restrict__ B,
                            const float* __restrict__ bias, float* __restrict__ C,
                            int M, int K, int N, int act) {
    __shared__ float As[16][72];
    __shared__ float Bs[16][72];
    int row0 = blockIdx.y * 64;
    int col0 = blockIdx.x * 64;
    int tid = threadIdx.x;
    int tx = tid & 15, ty = tid >> 4;
    float acc[4][4] = {};

    for (int k0 = 0; k0 < K; k0 += 16) {
        #pragma unroll
        for (int s = 0; s < 4; s++) {
            int m  = (tid >> 4) + s * 16;
            int kk = tid & 15;
            As[kk][m] = (k0 + kk < K) ? A[(size_t)(row0 + m) * K + k0 + kk] : 0.f;
        }
        #pragma unroll
        for (int s = 0; s < 4; s++) {
            int kk = (tid >> 6) + s * 4;
            int n  = tid & 63;
            float v = 0.f;
            if (k0 + kk < K && col0 + n < N) v = B[(size_t)(k0 + kk) * N + col0 + n];
            Bs[kk][n] = v;
        }
        __syncthreads();
        #pragma unroll
        for (int kk = 0; kk < 16; kk++) {
            float4 a4 = *(const float4*)&As[kk][ty * 4];
            float4 b4 = *(const float4*)&Bs[kk][tx * 4];
            float av[4] = {a4.x, a4.y, a4.z, a4.w};
            float bv[4] = {b4.x, b4.y, b4.z, b4.w};
            #pragma unroll
            for (int i = 0; i < 4; i++)
                #pragma unroll
                for (int j = 0; j < 4; j++)
                    acc[i][j] += av[i] * bv[j];
        }
        __syncthreads();
    }

    #pragma unroll
    for (int i = 0; i < 4; i++) {
        int r = row0 + ty * 4 + i;
        #pragma unroll
        for (int j = 0; j < 4; j++) {
            int c = col0 + tx * 4 + j;
            if (c < N) {
                float v = acc[i][j];
                if (bias) v += bias[c];
                if (act) v = lrelu(v);
                C[(size_t)r * N + c] = v;
            }
        }
    }
}

// ---------------------------------------------------------------------------
// 6) Fused edge second-linear + max-aggregation.
//    4 nodes (32 edges) per block; thread = output channel.
//    A[32][336] = lrelu(P_i + Q_j + b1) staged in smem; float4 reads.
// ---------------------------------------------------------------------------
__global__ void edge_kernel(const float* __restrict__ PQ, const int* __restrict__ nidx,
                            const float* __restrict__ b1, const float* __restrict__ W2,
                            const float* __restrict__ b2, float* __restrict__ out) {
    __shared__ float A[32 * DH];            // 43008 B
    int node0 = blockIdx.x * 4;
    int t = threadIdx.x;

    for (int kk = 0; kk < 32; kk++) {
        int i = node0 + (kk >> 3);
        int j = nidx[i * KNN + (kk & 7)];
        const float* P = PQ + (size_t)i * (2 * DH);
        const float* Q = PQ + (size_t)j * (2 * DH) + DH;
        for (int h = t; h < DH; h += 256) {
            A[kk * DH + h] = lrelu(P[h] + Q[h] + b1[h]);
        }
    }
    __syncthreads();

    int c = t;
    float acc[32];
    #pragma unroll
    for (int kk = 0; kk < 32; kk++) acc[kk] = 0.f;

    const float4* A4 = (const float4*)A;    // DH=336 -> 84 float4 per row, 16B aligned
    for (int rc = 0; rc < DH / 4; rc++) {
        int r = rc * 4;
        float w0 = W2[(r + 0) * DO + c];
        float w1v = W2[(r + 1) * DO + c];
        float w2v = W2[(r + 2) * DO + c];
        float w3v = W2[(r + 3) * DO + c];
        #pragma unroll
        for (int kk = 0; kk < 32; kk++) {
            float4 a = A4[kk * (DH / 4) + rc];
            acc[kk] += a.x * w0;
            acc[kk] += a.y * w1v;
            acc[kk] += a.z * w2v;
            acc[kk] += a.w * w3v;
        }
    }

    float bb = b2[c];
    #pragma unroll
    for (int g = 0; g < 4; g++) {
        float m = acc[g * 8];
        #pragma unroll
        for (int k = 1; k < 8; k++) m = fmaxf(m, acc[g * 8 + k]);
        out[(size_t)(node0 + g) * DO + c] = lrelu(m + bb);
    }
}

// ---------------------------------------------------------------------------
// 7) concat [x, x1, x2, x3, x4] -> [32768, 1030]
// ---------------------------------------------------------------------------
__global__ void concat_kernel(const float* __restrict__ x) {
    size_t e = (size_t)blockIdx.x * 256 + threadIdx.x;
    if (e >= (size_t)NNODES * CATDIM) return;
    int node = (int)(e / CATDIM);
    int col  = (int)(e % CATDIM);
    float v;
    if (col < F_IN) {
        v = x[node * F_IN + col];
    } else {
        int s  = (col - F_IN) >> 8;
        int cc = (col - F_IN) & 255;
        const float* src = (s == 0) ? g_x1 : (s == 1) ? g_x2 : (s == 2) ? g_x3 : g_x4;
        v = src[(size_t)node * DO + cc];
    }
    g_cat[e] = v;
}

// ---------------------------------------------------------------------------
// 8) mean pool over N, then tiny head
// ---------------------------------------------------------------------------
__global__ void pool_kernel(const float* __restrict__ H2) {
    int b = blockIdx.x;
    int c = threadIdx.x;
    float s = 0.f;
    for (int n = 0; n < NPTS; n++) s += H2[((size_t)b * NPTS + n) * DO + c];
    g_pool[b * DO + c] = s * (1.f / NPTS);
}

__global__ void final_kernel(const float* __restrict__ w1, const float* __restrict__ bb1,
                             const float* __restrict__ w2, const float* __restrict__ bb2,
                             float* __restrict__ out) {
    int b = blockIdx.x;
    int t = threadIdx.x;                    // 128 threads
    __shared__ float g1s[128];
    float s = bb1[t];
    for (int c = 0; c < DO; c++) s += g_pool[b * DO + c] * w1[c * 128 + t];
    g1s[t] = lrelu(s);
    __syncthreads();
    if (t < 3) {
        float o = bb2[t];
        for (int h = 0; h < 128; h++) o += g1s[h] * w2[h * 3 + t];
        out[b * 3 + t] = o;
    }
}

// ---------------------------------------------------------------------------
// Host orchestration
// ---------------------------------------------------------------------------
static void run_conv(const float* Xin, int F,
                     const float* w1, const float* b1,
                     const float* w2, const float* b2,
                     float* Xout, float* pq, int* pidx, float* pwcat) {
    sqnorm_kernel<<<NNODES / 8, 256>>>(Xin, F);
    dist_kernel<<<dim3(16, 16, BATCH), 256>>>(Xin, F);
    topk_kernel<<<NNODES, 256>>>();
    wcat_kernel<<<(F * DH + 255) / 256, 256>>>(w1, F);
    gemm_kernel<<<dim3((2 * DH + 63) / 64, NNODES / 64), 256>>>(
        Xin, pwcat, nullptr, pq, NNODES, F, 2 * DH, 0);
    edge_kernel<<<NNODES / 4, 256>>>(pq, pidx, b1, w2, b2, Xout);
}

extern "C" void kernel_launch(void* const* d_in, const int* in_sizes, int n_in,
                              void* d_out, int out_size) {
    (void)in_sizes; (void)n_in; (void)out_size;
    const float* x = (const float*)d_in[0];
    // d_in[1] = edge_index (unused), d_in[2] = batch (unused)
    const float* cw1[4] = {(const float*)d_in[3],  (const float*)d_in[7],
                           (const float*)d_in[11], (const float*)d_in[15]};
    const float* cb1[4] = {(const float*)d_in[4],  (const float*)d_in[8],
                           (const float*)d_in[12], (const float*)d_in[16]};
    const float* cw2[4] = {(const float*)d_in[5],  (const float*)d_in[9],
                           (const float*)d_in[13], (const float*)d_in[17]};
    const float* cb2[4] = {(const float*)d_in[6],  (const float*)d_in[10],
                           (const float*)d_in[14], (const float*)d_in[18]};
    const float* m1_w1 = (const float*)d_in[19];
    const float* m1_b1 = (const float*)d_in[20];
    const float* m1_w2 = (const float*)d_in[21];
    const float* m1_b2 = (const float*)d_in[22];
    const float* m2_w1 = (const float*)d_in[23];
    const float* m2_b1 = (const float*)d_in[24];
    const float* m2_w2 = (const float*)d_in[25];
    const float* m2_b2 = (const float*)d_in[26];

    float *px1, *px2, *px3, *px4, *ppq, *pwcat, *pcat, *ph, *ph2;
    int* pidx;
    cudaGetSymbolAddress((void**)&px1,   g_x1);
    cudaGetSymbolAddress((void**)&px2,   g_x2);
    cudaGetSymbolAddress((void**)&px3,   g_x3);
    cudaGetSymbolAddress((void**)&px4,   g_x4);
    cudaGetSymbolAddress((void**)&ppq,   g_PQ);
    cudaGetSymbolAddress((void**)&pwcat, g_wcat);
    cudaGetSymbolAddress((void**)&pcat,  g_cat);
    cudaGetSymbolAddress((void**)&ph,    g_h);
    cudaGetSymbolAddress((void**)&ph2,   g_h2);
    cudaGetSymbolAddress((void**)&pidx,  g_idx);

    run_conv(x,   F_IN, cw1[0], cb1[0], cw2[0], cb2[0], px1, ppq, pidx, pwcat);
    run_conv(px1, DO,   cw1[1], cb1[1], cw2[1], cb2[1], px2, ppq, pidx, pwcat);
    run_conv(px2, DO,   cw1[2], cb1[2], cw2[2], cb2[2], px3, ppq, pidx, pwcat);
    run_conv(px3, DO,   cw1[3], cb1[3], cw2[3], cb2[3], px4, ppq, pidx, pwcat);

    size_t catElems = (size_t)NNODES * CATDIM;
    concat_kernel<<<(unsigned)((catElems + 255) / 256), 256>>>(x);

    gemm_kernel<<<dim3((DH + 63) / 64, NNODES / 64), 256>>>(
        pcat, m1_w1, m1_b1, ph, NNODES, CATDIM, DH, 1);
    gemm_kernel<<<dim3((DO + 63) / 64, NNODES / 64), 256>>>(
        ph, m1_w2, m1_b2, ph2, NNODES, DH, DO, 1);

    pool_kernel<<<BATCH, 256>>>(ph2);
    final_kernel<<<BATCH, 128>>>(m2_w1, m2_b1, m2_w2, m2_b2, (float*)d_out);
}

// round 7
// speedup vs baseline: 1.4809x; 1.4809x over previous
#include <cuda_runtime.h>
#include <cstdint>

// ---------------------------------------------------------------------------
// Problem constants
// ---------------------------------------------------------------------------
#define BATCH    64
#define NPTS     512
#define NNODES   (BATCH * NPTS)   // 32768
#define KNN      8
#define F_IN     6
#define DH       336
#define DO       256
#define CATDIM   1030
#define CATPAD   1056             // g_cat row stride (x32); mma K uses 1040
#define DHPAD    352              // weight K stride (x32); mma K uses 336

// SMEM strides (floats) — chosen conflict-free for mma fragment loads
#define SA   20                   // A tile [128][16] stride
#define SBG  136                  // B tile [16][128] stride (tgemm)
#define SBE  264                  // B tile [16][256] stride (edge)

// ---------------------------------------------------------------------------
// Static device scratch
// ---------------------------------------------------------------------------
__device__ float g_sq   [NNODES];
__device__ float g_D    [(size_t)BATCH * NPTS * NPTS];     // 64 MB
__device__ int   g_idx  [NNODES * KNN];
__device__ float g_wcat [F_IN * (2 * DH)];                 // layer1 SIMT path
__device__ float g_wcatT[768 * 256];                       // [Npad=768][K=256]
__device__ float g_w2t  [256 * DHPAD];                     // [256][352]
__device__ float g_m1w1t[384 * CATPAD];                    // [384][1056]
__device__ float g_m1w2t[256 * DHPAD];                     // [256][352]
__device__ float g_PQ   [(size_t)NNODES * (2 * DH)];       // 88 MB
__device__ float g_x1   [(size_t)NNODES * DO];
__device__ float g_x2   [(size_t)NNODES * DO];
__device__ float g_x3   [(size_t)NNODES * DO];
__device__ float g_x4   [(size_t)NNODES * DO];
__device__ float g_cat  [(size_t)NNODES * CATPAD];         // 138 MB
__device__ float g_h    [(size_t)NNODES * DHPAD];
__device__ float g_h2   [(size_t)NNODES * DO];
__device__ float g_pool [BATCH * DO];

__device__ __forceinline__ float lrelu(float v) { return v >= 0.f ? v : 0.01f * v; }

__device__ __forceinline__ uint32_t to_tf32(float x) {
    uint32_t r;
    asm("cvt.rna.tf32.f32 %0, %1;" : "=r"(r) : "f"(x));
    return r;
}

// mma.sync m16n8k8 tf32: portable PTX (compute_80+), HMMA on sm_103
__device__ __forceinline__ void mma_tf32(float* c, const uint32_t* a, const uint32_t* b) {
    asm volatile(
        "mma.sync.aligned.m16n8k8.row.col.f32.tf32.tf32.f32 "
        "{%0,%1,%2,%3}, {%4,%5,%6,%7}, {%8,%9}, {%0,%1,%2,%3};"
        : "+f"(c[0]), "+f"(c[1]), "+f"(c[2]), "+f"(c[3])
        : "r"(a[0]), "r"(a[1]), "r"(a[2]), "r"(a[3]), "r"(b[0]), "r"(b[1]));
}

// ---------------------------------------------------------------------------
// SIMT helper kernels
// ---------------------------------------------------------------------------
__global__ void sqnorm_kernel(const float* __restrict__ X, int F) {
    int node = blockIdx.x * 8 + (threadIdx.x >> 5);
    int lane = threadIdx.x & 31;
    const float* row = X + (size_t)node * F;
    float s = 0.f;
    for (int f = lane; f < F; f += 32) { float v = row[f]; s += v * v; }
    #pragma unroll
    for (int o = 16; o; o >>= 1) s += __shfl_xor_sync(0xFFFFFFFFu, s, o);
    if (lane == 0) g_sq[node] = s;
}

__global__ void dist_kernel(const float* __restrict__ X, int F) {  // layer-1 (F=6)
    __shared__ float As[32][17];
    __shared__ float Bs[32][17];
    int b  = blockIdx.z;
    int i0 = blockIdx.y * 32;
    int j0 = blockIdx.x * 32;
    int tid = threadIdx.x;
    int tx = tid & 15, ty = tid >> 4;
    float a00 = 0.f, a01 = 0.f, a10 = 0.f, a11 = 0.f;
    for (int f0 = 0; f0 < F; f0 += 16) {
        #pragma unroll
        for (int s = 0; s < 2; s++) {
            int r = (tid >> 4) + s * 16, c = tid & 15;
            float av = 0.f, bv = 0.f;
            if (f0 + c < F) {
                av = X[((size_t)(b * NPTS + i0 + r)) * F + f0 + c];
                bv = X[((size_t)(b * NPTS + j0 + r)) * F + f0 + c];
            }
            As[r][c] = av; Bs[r][c] = bv;
        }
        __syncthreads();
        #pragma unroll
        for (int ff = 0; ff < 16; ff++) {
            float x0 = As[2 * ty][ff], x1 = As[2 * ty + 1][ff];
            float y0 = Bs[2 * tx][ff], y1 = Bs[2 * tx + 1][ff];
            a00 += x0 * y0; a01 += x0 * y1; a10 += x1 * y0; a11 += x1 * y1;
        }
        __syncthreads();
    }
    int gi = i0 + 2 * ty, gj = j0 + 2 * tx;
    float si0 = g_sq[b * NPTS + gi], si1 = g_sq[b * NPTS + gi + 1];
    float sj0 = g_sq[b * NPTS + gj], sj1 = g_sq[b * NPTS + gj + 1];
    size_t base = ((size_t)b * NPTS + gi) * NPTS + gj;
    g_D[base]            = si0 + sj0 - 2.f * a00;
    g_D[base + 1]        = si0 + sj1 - 2.f * a01;
    g_D[base + NPTS]     = si1 + sj0 - 2.f * a10;
    g_D[base + NPTS + 1] = si1 + sj1 - 2.f * a11;
}

__global__ void topk_kernel() {
    int row = blockIdx.x;
    int b = row >> 9;
    const float* drow = g_D + (size_t)row * NPTS;
    __shared__ float sv[NPTS];
    __shared__ float rv[256];
    __shared__ int   ri[256];
    int t = threadIdx.x;
    sv[t] = drow[t];
    sv[t + 256] = drow[t + 256];
    __syncthreads();
    for (int k = 0; k < KNN; k++) {
        float v0 = sv[t], v1 = sv[t + 256];
        float bv; int bi;
        if (v0 <= v1) { bv = v0; bi = t; } else { bv = v1; bi = t + 256; }
        rv[t] = bv; ri[t] = bi;
        __syncthreads();
        for (int s = 128; s > 0; s >>= 1) {
            if (t < s) {
                float ov = rv[t + s]; int oi = ri[t + s];
                if (ov < rv[t] || (ov == rv[t] && oi < ri[t])) { rv[t] = ov; ri[t] = oi; }
            }
            __syncthreads();
        }
        if (t == 0) { g_idx[row * KNN + k] = b * NPTS + ri[0]; sv[ri[0]] = 3.4e38f; }
        __syncthreads();
    }
}

__global__ void wcat_kernel(const float* __restrict__ w1, int F) {
    int e = blockIdx.x * blockDim.x + threadIdx.x;
    if (e >= F * DH) return;
    int f = e / DH, h = e % DH;
    float top = w1[f * DH + h];
    float bot = w1[(F + f) * DH + h];
    g_wcat[f * (2 * DH) + h]      = top - bot;
    g_wcat[f * (2 * DH) + DH + h] = bot;
}

__global__ void wcatT_kernel(const float* __restrict__ w1) {  // [768][256], K-major
    int e = blockIdx.x * blockDim.x + threadIdx.x;
    if (e >= 768 * 256) return;
    int h = e >> 8, f = e & 255;
    float v = 0.f;
    if (h < DH)            v = w1[f * DH + h] - w1[(256 + f) * DH + h];
    else if (h < 2 * DH)   v = w1[(256 + f) * DH + (h - DH)];
    g_wcatT[e] = v;
}

__global__ void transpose_pad(const float* __restrict__ src, float* __restrict__ dst,
                              int K, int N, int Kpad, int Npad) {
    int e = blockIdx.x * blockDim.x + threadIdx.x;
    if (e >= Kpad * Npad) return;
    int n = e / Kpad, k = e % Kpad;
    dst[e] = (k < K && n < N) ? src[(size_t)k * N + n] : 0.f;
}

// SIMT GEMM (layer-1 PQ only, K=6)
__global__ void gemm_kernel(const float* __restrict__ A, const float* __restrict__ B,
                            float* __restrict__ C, int M, int K, int N) {
    __shared__ float As[16][72];
    __shared__ float Bs[16][72];
    int row0 = blockIdx.y * 64, col0 = blockIdx.x * 64;
    int tid = threadIdx.x;
    int tx = tid & 15, ty = tid >> 4;
    float acc[4][4] = {};
    for (int k0 = 0; k0 < K; k0 += 16) {
        #pragma unroll
        for (int s = 0; s < 4; s++) {
            int m = (tid >> 4) + s * 16, kk = tid & 15;
            As[kk][m] = (k0 + kk < K) ? A[(size_t)(row0 + m) * K + k0 + kk] : 0.f;
        }
        #pragma unroll
        for (int s = 0; s < 4; s++) {
            int kk = (tid >> 6) + s * 4, n = tid & 63;
            float v = 0.f;
            if (k0 + kk < K && col0 + n < N) v = B[(size_t)(k0 + kk) * N + col0 + n];
            Bs[kk][n] = v;
        }
        __syncthreads();
        #pragma unroll
        for (int kk = 0; kk < 16; kk++) {
            float4 a4 = *(const float4*)&As[kk][ty * 4];
            float4 b4 = *(const float4*)&Bs[kk][tx * 4];
            float av[4] = {a4.x, a4.y, a4.z, a4.w};
            float bv[4] = {b4.x, b4.y, b4.z, b4.w};
            #pragma unroll
            for (int i = 0; i < 4; i++)
                #pragma unroll
                for (int j = 0; j < 4; j++) acc[i][j] += av[i] * bv[j];
        }
        __syncthreads();
    }
    #pragma unroll
    for (int i = 0; i < 4; i++) {
        int r = row0 + ty * 4 + i;
        #pragma unroll
        for (int j = 0; j < 4; j++) {
            int c = col0 + tx * 4 + j;
            if (c < N) C[(size_t)r * N + c] = acc[i][j];
        }
    }
}

// ---------------------------------------------------------------------------
// Tensor-core tf32 GEMM via mma.sync: C[M,N] = A[M,K] @ Bt[N,K]^T
// Block tile 128x128, 256 threads (8 warps, 2x4), warp tile 64x32.
// K consumed in chunks of 16 (KC chunks). All K/16 exact (no tail).
// mode 0: plain; 1: bias+lrelu; 2: dist epilogue (sq_i + sq_j - 2*acc)
// ---------------------------------------------------------------------------
__global__ __launch_bounds__(256) void tgemm(
    const float* __restrict__ A, int lda, long long aStride,
    const float* __restrict__ Bt, int ldb, long long bStride,
    float* __restrict__ C, int ldc, long long cStride,
    int N, int KC, int mode, const float* __restrict__ bias,
    const float* __restrict__ sq, int ldcPad)
{
    __shared__ uint32_t As[128 * SA];    // 10240 B
    __shared__ uint32_t Bs[16 * SBG];    //  8704 B

    int t = threadIdx.x;
    int wid = t >> 5, lane = t & 31;
    int wm = wid & 1, wn = wid >> 1;           // 2 x 4 warp grid
    int m0 = blockIdx.y * 128;
    int n0 = blockIdx.x * 128;
    int z  = blockIdx.z;
    A  += (size_t)z * aStride;
    Bt += (size_t)z * bStride;
    C  += (size_t)z * cStride;

    float acc[4][4][4] = {};                   // [mt][nt][frag]
    int r4 = t >> 2, q = t & 3;
    int g = lane >> 2, tg = lane & 3;

    for (int c = 0; c < KC; c++) {
        int k0 = c * 16;
        #pragma unroll
        for (int s = 0; s < 2; s++) {          // A: 128 rows x 16 k
            int r = r4 + s * 64;
            float4 v = *(const float4*)(A + (size_t)(m0 + r) * lda + k0 + q * 4);
            uint32_t* dst = &As[r * SA + q * 4];
            dst[0] = to_tf32(v.x); dst[1] = to_tf32(v.y);
            dst[2] = to_tf32(v.z); dst[3] = to_tf32(v.w);
        }
        #pragma unroll
        for (int s = 0; s < 2; s++) {          // B: transpose 128 n x 16 k
            int n = r4 + s * 64;
            float4 v = *(const float4*)(Bt + (size_t)(n0 + n) * ldb + k0 + q * 4);
            Bs[(q * 4 + 0) * SBG + n] = to_tf32(v.x);
            Bs[(q * 4 + 1) * SBG + n] = to_tf32(v.y);
            Bs[(q * 4 + 2) * SBG + n] = to_tf32(v.z);
            Bs[(q * 4 + 3) * SBG + n] = to_tf32(v.w);
        }
        __syncthreads();
        #pragma unroll
        for (int ks = 0; ks < 2; ks++) {
            int k = ks * 8;
            uint32_t af[4][4], bf[4][2];
            #pragma unroll
            for (int mt = 0; mt < 4; mt++) {
                int r = wm * 64 + mt * 16 + g;
                af[mt][0] = As[r * SA + k + tg];
                af[mt][1] = As[(r + 8) * SA + k + tg];
                af[mt][2] = As[r * SA + k + tg + 4];
                af[mt][3] = As[(r + 8) * SA + k + tg + 4];
            }
            #pragma unroll
            for (int nt = 0; nt < 4; nt++) {
                int n = wn * 32 + nt * 8 + g;
                bf[nt][0] = Bs[(k + tg) * SBG + n];
                bf[nt][1] = Bs[(k + tg + 4) * SBG + n];
            }
            #pragma unroll
            for (int mt = 0; mt < 4; mt++)
                #pragma unroll
                for (int nt = 0; nt < 4; nt++)
                    mma_tf32(acc[mt][nt], af[mt], bf[nt]);
        }
        __syncthreads();
    }

    // epilogue
    #pragma unroll
    for (int mt = 0; mt < 4; mt++) {
        int r0 = m0 + wm * 64 + mt * 16 + g;
        #pragma unroll
        for (int nt = 0; nt < 4; nt++) {
            int cb = n0 + wn * 32 + nt * 8 + tg * 2;
            #pragma unroll
            for (int e = 0; e < 4; e++) {
                int row = r0 + ((e >= 2) ? 8 : 0);
                int col = cb + (e & 1);
                if (col < ldcPad) {
                    float x = acc[mt][nt][e];
                    if (mode == 2) {
                        x = sq[(size_t)z * NPTS + row] + sq[(size_t)z * NPTS + col] - 2.f * x;
                    } else if (col >= N) {
                        x = 0.f;
                    } else if (mode == 1) {
                        x = lrelu(x + bias[col]);
                    }
                    C[(size_t)row * ldc + col] = x;
                }
            }
        }
    }
}

// ---------------------------------------------------------------------------
// Fused edge-MLP second linear + max-aggregation via mma.sync.
// Block: 16 nodes = 128 edges x all 256 channels. 512 threads (16 warps, 4x4),
// warp tile 32 edges x 64 channels. A-tile = lrelu(P_i + Q_j + b1) built
// per k-chunk directly in SMEM (tf32). K = 336 = 21 chunks x 16.
// Epilogue: max over 8 edges/node via shfl, + b2, lrelu.
// ---------------------------------------------------------------------------
__global__ __launch_bounds__(512) void edge_mma(
    const float* __restrict__ PQ, const int* __restrict__ nidx,
    const float* __restrict__ b1, const float* __restrict__ b2,
    float* __restrict__ out)
{
    __shared__ uint32_t As[128 * SA];    // 10240 B
    __shared__ uint32_t Bs[16 * SBE];    // 16896 B
    __shared__ int sj[128];

    int t = threadIdx.x;
    int wid = t >> 5, lane = t & 31;
    int wm = wid & 3, wn = wid >> 2;           // 4 x 4 warp grid
    int node0 = blockIdx.x * 16;
    if (t < 128) sj[t] = nidx[(node0 + (t >> 3)) * KNN + (t & 7)];
    __syncthreads();

    float acc[2][8][4] = {};                   // [mt][nt][frag]
    int e4 = t >> 2, q = t & 3;                // e4 = edge row, q = k-quad
    int g = lane >> 2, tg = lane & 3;
    int ii = node0 + (e4 >> 3);
    int jj = sj[e4];

    for (int c = 0; c < 21; c++) {
        int k0 = c * 16;
        int h = k0 + q * 4;
        {   // A: one float4 per thread (512 = 128 edges x 4 quads)
            float4 p  = *(const float4*)(PQ + (size_t)ii * (2 * DH) + h);
            float4 qq = *(const float4*)(PQ + (size_t)jj * (2 * DH) + DH + h);
            float4 bb = *(const float4*)(b1 + h);
            uint32_t* dst = &As[e4 * SA + q * 4];
            dst[0] = to_tf32(lrelu(p.x + qq.x + bb.x));
            dst[1] = to_tf32(lrelu(p.y + qq.y + bb.y));
            dst[2] = to_tf32(lrelu(p.z + qq.z + bb.z));
            dst[3] = to_tf32(lrelu(p.w + qq.w + bb.w));
        }
        #pragma unroll
        for (int s = 0; s < 2; s++) {          // B: 256 weight rows
            int n = e4 + s * 128;
            float4 v = *(const float4*)(g_w2t + (size_t)n * DHPAD + h);
            Bs[(q * 4 + 0) * SBE + n] = to_tf32(v.x);
            Bs[(q * 4 + 1) * SBE + n] = to_tf32(v.y);
            Bs[(q * 4 + 2) * SBE + n] = to_tf32(v.z);
            Bs[(q * 4 + 3) * SBE + n] = to_tf32(v.w);
        }
        __syncthreads();
        #pragma unroll
        for (int ks = 0; ks < 2; ks++) {
            int k = ks * 8;
            uint32_t af[2][4], bf[8][2];
            #pragma unroll
            for (int mt = 0; mt < 2; mt++) {
                int r = wm * 32 + mt * 16 + g;
                af[mt][0] = As[r * SA + k + tg];
                af[mt][1] = As[(r + 8) * SA + k + tg];
                af[mt][2] = As[r * SA + k + tg + 4];
                af[mt][3] = As[(r + 8) * SA + k + tg + 4];
            }
            #pragma unroll
            for (int nt = 0; nt < 8; nt++) {
                int n = wn * 64 + nt * 8 + g;
                bf[nt][0] = Bs[(k + tg) * SBE + n];
                bf[nt][1] = Bs[(k + tg + 4) * SBE + n];
            }
            #pragma unroll
            for (int mt = 0; mt < 2; mt++)
                #pragma unroll
                for (int nt = 0; nt < 8; nt++)
                    mma_tf32(acc[mt][nt], af[mt], bf[nt]);
        }
        __syncthreads();
    }

    // epilogue: rows 0-7 of each 16-row tile = one node, rows 8-15 = next node.
    // Reduce max over lane-groups (g = lane>>2) via xor 4,8,16.
    #pragma unroll
    for (int mt = 0; mt < 2; mt++) {
        int node = node0 + wm * 4 + mt * 2;
        #pragma unroll
        for (int nt = 0; nt < 8; nt++) {
            float* a = acc[mt][nt];
            #pragma unroll
            for (int e = 0; e < 4; e++) {
                float v = a[e];
                v = fmaxf(v, __shfl_xor_sync(0xFFFFFFFFu, v, 4));
                v = fmaxf(v, __shfl_xor_sync(0xFFFFFFFFu, v, 8));
                v = fmaxf(v, __shfl_xor_sync(0xFFFFFFFFu, v, 16));
                a[e] = v;
            }
            if (lane < 4) {
                int col = wn * 64 + nt * 8 + lane * 2;
                out[(size_t)node * DO + col]           = lrelu(a[0] + b2[col]);
                out[(size_t)node * DO + col + 1]       = lrelu(a[1] + b2[col + 1]);
                out[(size_t)(node + 1) * DO + col]     = lrelu(a[2] + b2[col]);
                out[(size_t)(node + 1) * DO + col + 1] = lrelu(a[3] + b2[col + 1]);
            }
        }
    }
}

// ---------------------------------------------------------------------------
// concat (padded to 1056), pool, final head
// ---------------------------------------------------------------------------
__global__ void concat_kernel(const float* __restrict__ x) {
    size_t e = (size_t)blockIdx.x * 256 + threadIdx.x;
    if (e >= (size_t)NNODES * CATPAD) return;
    int node = (int)(e / CATPAD);
    int col  = (int)(e % CATPAD);
    float v = 0.f;
    if (col < F_IN) v = x[node * F_IN + col];
    else if (col < CATDIM) {
        int s  = (col - F_IN) >> 8;
        int cc = (col - F_IN) & 255;
        const float* src = (s == 0) ? g_x1 : (s == 1) ? g_x2 : (s == 2) ? g_x3 : g_x4;
        v = src[(size_t)node * DO + cc];
    }
    g_cat[e] = v;
}

__global__ void pool_kernel(const float* __restrict__ H2) {
    int b = blockIdx.x, c = threadIdx.x;
    float s = 0.f;
    for (int n = 0; n < NPTS; n++) s += H2[((size_t)b * NPTS + n) * DO + c];
    g_pool[b * DO + c] = s * (1.f / NPTS);
}

__global__ void final_kernel(const float* __restrict__ w1, const float* __restrict__ bb1,
                             const float* __restrict__ w2, const float* __restrict__ bb2,
                             float* __restrict__ out) {
    int b = blockIdx.x, t = threadIdx.x;
    __shared__ float g1s[128];
    float s = bb1[t];
    for (int c = 0; c < DO; c++) s += g_pool[b * DO + c] * w1[c * 128 + t];
    g1s[t] = lrelu(s);
    __syncthreads();
    if (t < 3) {
        float o = bb2[t];
        for (int h = 0; h < 128; h++) o += g1s[h] * w2[h * 3 + t];
        out[b * 3 + t] = o;
    }
}

// ---------------------------------------------------------------------------
// Host orchestration
// ---------------------------------------------------------------------------
extern "C" void kernel_launch(void* const* d_in, const int* in_sizes, int n_in,
                              void* d_out, int out_size) {
    (void)in_sizes; (void)n_in; (void)out_size;
    const float* x = (const float*)d_in[0];
    const float* cw1[4] = {(const float*)d_in[3],  (const float*)d_in[7],
                           (const float*)d_in[11], (const float*)d_in[15]};
    const float* cb1[4] = {(const float*)d_in[4],  (const float*)d_in[8],
                           (const float*)d_in[12], (const float*)d_in[16]};
    const float* cw2[4] = {(const float*)d_in[5],  (const float*)d_in[9],
                           (const float*)d_in[13], (const float*)d_in[17]};
    const float* cb2[4] = {(const float*)d_in[6],  (const float*)d_in[10],
                           (const float*)d_in[14], (const float*)d_in[18]};
    const float* m1_w1 = (const float*)d_in[19];
    const float* m1_b1 = (const float*)d_in[20];
    const float* m1_w2 = (const float*)d_in[21];
    const float* m1_b2 = (const float*)d_in[22];
    const float* m2_w1 = (const float*)d_in[23];
    const float* m2_b1 = (const float*)d_in[24];
    const float* m2_w2 = (const float*)d_in[25];
    const float* m2_b2 = (const float*)d_in[26];

    float *px[4], *ppq, *pwcat, *pwcatT, *pw2t, *pm1w1t, *pm1w2t, *pcat, *ph, *ph2, *psq;
    int* pidx;
    cudaGetSymbolAddress((void**)&px[0],  g_x1);
    cudaGetSymbolAddress((void**)&px[1],  g_x2);
    cudaGetSymbolAddress((void**)&px[2],  g_x3);
    cudaGetSymbolAddress((void**)&px[3],  g_x4);
    cudaGetSymbolAddress((void**)&ppq,    g_PQ);
    cudaGetSymbolAddress((void**)&pwcat,  g_wcat);
    cudaGetSymbolAddress((void**)&pwcatT, g_wcatT);
    cudaGetSymbolAddress((void**)&pw2t,   g_w2t);
    cudaGetSymbolAddress((void**)&pm1w1t, g_m1w1t);
    cudaGetSymbolAddress((void**)&pm1w2t, g_m1w2t);
    cudaGetSymbolAddress((void**)&pcat,   g_cat);
    cudaGetSymbolAddress((void**)&ph,     g_h);
    cudaGetSymbolAddress((void**)&ph2,    g_h2);
    cudaGetSymbolAddress((void**)&psq,    g_sq);
    cudaGetSymbolAddress((void**)&pidx,   g_idx);

    float* pD; cudaGetSymbolAddress((void**)&pD, g_D);

    for (int layer = 0; layer < 4; layer++) {
        const float* Xin = (layer == 0) ? x : px[layer - 1];
        int F = (layer == 0) ? F_IN : DO;

        sqnorm_kernel<<<NNODES / 8, 256>>>(Xin, F);
        if (layer == 0) {
            dist_kernel<<<dim3(16, 16, BATCH), 256>>>(Xin, F);
        } else {
            // D[b] = sq_i + sq_j - 2 * X[b] X[b]^T   (A = B = X, K-major)
            tgemm<<<dim3(4, 4, BATCH), 256>>>(
                Xin, DO, (long long)NPTS * DO,
                Xin, DO, (long long)NPTS * DO,
                pD, NPTS, (long long)NPTS * NPTS,
                NPTS, DO / 16, 2, nullptr, psq, NPTS);
        }
        topk_kernel<<<NNODES, 256>>>();

        if (layer == 0) {
            wcat_kernel<<<(F_IN * DH + 255) / 256, 256>>>(cw1[0], F_IN);
            gemm_kernel<<<dim3((2 * DH + 63) / 64, NNODES / 64), 256>>>(
                Xin, pwcat, ppq, NNODES, F_IN, 2 * DH);
        } else {
            wcatT_kernel<<<(768 * 256) / 256, 256>>>(cw1[layer]);
            tgemm<<<dim3(6, NNODES / 128, 1), 256>>>(
                Xin, DO, 0, pwcatT, DO, 0,
                ppq, 2 * DH, 0, 2 * DH, DO / 16, 0, nullptr, nullptr, 2 * DH);
        }
        transpose_pad<<<(256 * DHPAD + 255) / 256, 256>>>(cw2[layer], pw2t, DH, DO, DHPAD, DO);
        edge_mma<<<NNODES / 16, 512>>>(ppq, pidx, cb1[layer], cb2[layer], px[layer]);
    }

    size_t catElems = (size_t)NNODES * CATPAD;
    concat_kernel<<<(unsigned)((catElems + 255) / 256), 256>>>(x);

    transpose_pad<<<(384 * CATPAD + 255) / 256, 256>>>(m1_w1, pm1w1t, CATDIM, DH, CATPAD, 384);
    transpose_pad<<<(256 * DHPAD + 255) / 256, 256>>>(m1_w2, pm1w2t, DH, DO, DHPAD, DO);

    // h = lrelu(cat @ m1_w1 + b1): K = 1040 (cols 1030..1039 zero-padded)
    tgemm<<<dim3(3, NNODES / 128, 1), 256>>>(
        pcat, CATPAD, 0, pm1w1t, CATPAD, 0,
        ph, DHPAD, 0, DH, 1040 / 16, 1, m1_b1, nullptr, DHPAD);
    // h2 = lrelu(h @ m1_w2 + b2): K = 336
    tgemm<<<dim3(2, NNODES / 128, 1), 256>>>(
        ph, DHPAD, 0, pm1w2t, DHPAD, 0,
        ph2, DO, 0, DO, DH / 16, 1, m1_b2, nullptr, DO);

    pool_kernel<<<BATCH, 256>>>(ph2);
    final_kernel<<<BATCH, 128>>>(m2_w1, m2_b1, m2_w2, m2_b2, (float*)d_out);
}